// round 11
// baseline (speedup 1.0000x reference)
#include <cuda_runtime.h>
#include <cuda_fp16.h>
#include <math_constants.h>
#include <cstdint>

#define BATCH 8192
#define DIM 128
#define MARGIN 0.2f
#define EPSV 1e-6f

#define NJT 64
#define NIT 64
#define NJOBS (NIT * NJT)
#define GRID_MAIN 152
#define NTHREADS 512

// SMEM: fp16 tiles, row stride 272 B (conflict-free LDSM), double-buffered B
#define ROWB 272
#define TILE_BYTES (128 * ROWB)          // 34816
#define SO_SJ   0                        // 2 x 512 B (j row-constants)
#define SO_MASK 1024                     // 2 x 128 B
#define SO_AHI  2048
#define SO_ALO  (SO_AHI + TILE_BYTES)    // 36864
#define SO_B0   (SO_ALO + TILE_BYTES)    // 71680
#define SO_B1   (SO_B0 + TILE_BYTES)     // 106496
#define SMEM_TOTAL (SO_B1 + TILE_BYTES)  // 141312

// ---------------------------------------------------------------------------
// Scratch (device allocation forbidden)
// ---------------------------------------------------------------------------
__device__ float g_r1[BATCH];
__device__ float g_r2[BATCH];
__device__ unsigned int g_posmax[BATCH];   // float bits of max sq-dist (positives)
__device__ unsigned int g_negmin[BATCH];   // float bits of min sq-dist (negatives)
__device__ __align__(16) unsigned char g_tmask[BATCH];
__device__ unsigned int g_done;
__device__ __align__(16) __half g_e1hi[BATCH * DIM];
__device__ __align__(16) __half g_e1lo[BATCH * DIM];
__device__ __align__(16) __half g_e2hi[BATCH * DIM];

// ---------------------------------------------------------------------------
// PTX helpers (base ISA: ldmatrix, mma.sync, cp.async)
// ---------------------------------------------------------------------------
__device__ __forceinline__ uint32_t smem_to_u32(const void* p) {
    uint32_t a;
    asm("{ .reg .u64 t; cvta.to.shared.u64 t, %1; cvt.u32.u64 %0, t; }" : "=r"(a) : "l"(p));
    return a;
}
__device__ __forceinline__ void ldsm4(uint32_t* r, uint32_t addr) {
    asm volatile("ldmatrix.sync.aligned.m8n8.x4.shared.b16 {%0,%1,%2,%3}, [%4];"
                 : "=r"(r[0]), "=r"(r[1]), "=r"(r[2]), "=r"(r[3]) : "r"(addr));
}
__device__ __forceinline__ void mma16816(float* c, const uint32_t* a,
                                         uint32_t b0, uint32_t b1) {
    asm volatile(
        "mma.sync.aligned.m16n8k16.row.col.f32.f16.f16.f32 "
        "{%0,%1,%2,%3}, {%4,%5,%6,%7}, {%8,%9}, {%0,%1,%2,%3};"
        : "+f"(c[0]), "+f"(c[1]), "+f"(c[2]), "+f"(c[3])
        : "r"(a[0]), "r"(a[1]), "r"(a[2]), "r"(a[3]), "r"(b0), "r"(b1));
}
__device__ __forceinline__ void cp16(uint32_t dst, const void* src) {
    asm volatile("cp.async.cg.shared.global [%0], [%1], 16;" :: "r"(dst), "l"(src));
}
#define CP_COMMIT() asm volatile("cp.async.commit_group;" ::: "memory")
#define CP_WAIT_ALL() asm volatile("cp.async.wait_group 0;" ::: "memory")

// ---------------------------------------------------------------------------
// prep: row constants, reduction init, mask (int32 target), fp16 hi/lo split.
// One warp per row, 2*BATCH rows. Also resets the completion ticket.
// ---------------------------------------------------------------------------
__global__ void prep_kernel(const float* __restrict__ e1,
                            const float* __restrict__ e2,
                            const int* __restrict__ t32) {
    if (blockIdx.x == 0 && threadIdx.x == 0) g_done = 0u;
    int warp = (blockIdx.x * blockDim.x + threadIdx.x) >> 5;
    int lane = threadIdx.x & 31;
    if (warp >= 2 * BATCH) return;
    bool is1 = (warp < BATCH);
    int row = is1 ? warp : warp - BATCH;
    const float* base = is1 ? e1 : e2;
    float4 v = reinterpret_cast<const float4*>(base + (size_t)row * DIM)[lane];

    float xs[4] = {v.x, v.y, v.z, v.w};
    __half h[4], l[4];
    #pragma unroll
    for (int i = 0; i < 4; i++) {
        h[i] = __float2half_rn(xs[i]);
        l[i] = __float2half_rn(xs[i] - __half2float(h[i]));
    }
    int idx = row * DIM + lane * 4;
    __half2 hp0; hp0.x = h[0]; hp0.y = h[1];
    __half2 hp1; hp1.x = h[2]; hp1.y = h[3];
    __half* dh = is1 ? g_e1hi : g_e2hi;
    *reinterpret_cast<__half2*>(&dh[idx])     = hp0;
    *reinterpret_cast<__half2*>(&dh[idx + 2]) = hp1;
    if (is1) {
        __half2 lp0; lp0.x = l[0]; lp0.y = l[1];
        __half2 lp1; lp1.x = l[2]; lp1.y = l[3];
        *reinterpret_cast<__half2*>(&g_e1lo[idx])     = lp0;
        *reinterpret_cast<__half2*>(&g_e1lo[idx + 2]) = lp1;
    }

    float s = v.x + v.y + v.z + v.w;
    float q = v.x * v.x + v.y * v.y + v.z * v.z + v.w * v.w;
    #pragma unroll
    for (int o = 16; o > 0; o >>= 1) {
        s += __shfl_xor_sync(0xffffffffu, s, o);
        q += __shfl_xor_sync(0xffffffffu, q, o);
    }
    if (lane == 0) {
        if (is1) {
            g_r1[row] = q + 2.0f * EPSV * s + (float)DIM * EPSV * EPSV;
            g_posmax[row] = 0xFF800000u;
            g_negmin[row] = 0x7F800000u;
            g_tmask[row] = (t32[row] == 1) ? 1 : 0;
        } else {
            g_r2[row] = q - 2.0f * EPSV * s;
        }
    }
}

// ---------------------------------------------------------------------------
// Main: persistent CTAs, fp16-split 2-pass mma.sync GEMM + sq-dist max/min.
// 16 warps as 4(m) x 4(n); warp tile 32x32 (4 warps/SMSP for latency hiding).
// B double-buffered via cp.async. Last CTA folds in finalization.
// ---------------------------------------------------------------------------
extern __shared__ char sm_dyn[];

__device__ __forceinline__ void issue_tile(uint32_t smb, int off, const __half* g,
                                           int row0, int tid) {
    #pragma unroll
    for (int t = 0; t < 4; t++) {
        int i = tid + t * NTHREADS;
        int row = i >> 4;
        int c = i & 15;
        cp16(smb + off + row * ROWB + c * 16, g + (size_t)(row0 + row) * DIM + c * 8);
    }
}

__global__ __launch_bounds__(NTHREADS, 1) void bht_mma_kernel(float* __restrict__ out) {
    char* sm = sm_dyn;
    const uint32_t smb = smem_to_u32(sm);
    float* s_j = reinterpret_cast<float*>(sm + SO_SJ);
    unsigned char* s_mask = reinterpret_cast<unsigned char*>(sm + SO_MASK);

    const int tid = threadIdx.x;
    const int wid = tid >> 5;
    const int lane = tid & 31;
    const int tq = lane >> 2;
    const int tr = lane & 3;
    const int warp_m = (wid & 3) * 32;
    const int warp_n = (wid >> 2) * 32;

    const int a_off = (warp_m + (lane & 15)) * ROWB + (lane >> 4) * 16;
    const int b_off = (warp_n + (lane & 7) + ((lane >> 4) << 3)) * ROWB
                    + ((lane >> 3) & 1) * 16;

    const int job0 = (NJOBS * blockIdx.x) / GRID_MAIN;
    const int jend = (NJOBS * (blockIdx.x + 1)) / GRID_MAIN;

    int cur_i = -1, i0 = 0, p = 0;
    float r1v[4], pmax[4], nmin[4];

    // prologue: first job's B tile + row constants into slot 0
    {
        const int j0 = (job0 & (NJT - 1)) * 128;
        issue_tile(smb, SO_B0, g_e2hi, j0, tid);
        if (tid < 32) cp16(smb + SO_SJ + tid * 16, g_r2 + j0 + tid * 4);
        else if (tid < 40) cp16(smb + SO_MASK + (tid - 32) * 16, g_tmask + j0 + (tid - 32) * 16);
        CP_COMMIT();
    }

    for (int job = job0; job < jend; ++job) {
        const int it = job >> 6;
        bool ichg = (it != cur_i);

        if (ichg) {
            // flush previous strip
            if (cur_i >= 0) {
                #pragma unroll
                for (int idx = 0; idx < 4; idx++) {
                    float pv = pmax[idx], nv = nmin[idx];
                    pv = fmaxf(pv, __shfl_xor_sync(0xffffffffu, pv, 1));
                    pv = fmaxf(pv, __shfl_xor_sync(0xffffffffu, pv, 2));
                    nv = fminf(nv, __shfl_xor_sync(0xffffffffu, nv, 1));
                    nv = fminf(nv, __shfl_xor_sync(0xffffffffu, nv, 2));
                    if (tr == 0) {
                        int row = i0 + warp_m + (idx >> 1) * 16 + (idx & 1) * 8 + tq;
                        atomicMax(reinterpret_cast<int*>(&g_posmax[row]), __float_as_int(pv));
                        atomicMin(reinterpret_cast<int*>(&g_negmin[row]), __float_as_int(nv));
                    }
                }
            }
            i0 = it * 128;
            __syncthreads();   // all readers done with old A before overwrite
            issue_tile(smb, SO_AHI, g_e1hi, i0, tid);
            issue_tile(smb, SO_ALO, g_e1lo, i0, tid);
            CP_COMMIT();
        }

        CP_WAIT_ALL();
        __syncthreads();       // slot p (and A, if reloaded) visible to all

        if (ichg) {
            #pragma unroll
            for (int idx = 0; idx < 4; idx++) {
                int row = i0 + warp_m + (idx >> 1) * 16 + (idx & 1) * 8 + tq;
                r1v[idx] = g_r1[row];
                pmax[idx] = -CUDART_INF_F;
                nmin[idx] = CUDART_INF_F;
            }
            cur_i = it;
        }

        // issue next job's B into the other slot (overlaps with compute below)
        if (job + 1 < jend) {
            const int nj0 = ((job + 1) & (NJT - 1)) * 128;
            const int so_b = p ? SO_B0 : SO_B1;
            const int so_j = SO_SJ + (p ^ 1) * 512;
            const int so_m = SO_MASK + (p ^ 1) * 128;
            issue_tile(smb, so_b, g_e2hi, nj0, tid);
            if (tid < 32) cp16(smb + so_j + tid * 16, g_r2 + nj0 + tid * 4);
            else if (tid < 40) cp16(smb + so_m + (tid - 32) * 16, g_tmask + nj0 + (tid - 32) * 16);
            CP_COMMIT();
        }

        // ---- compute on slot p ----
        const uint32_t bbase = smb + (p ? SO_B1 : SO_B0) + b_off;
        const uint32_t ahibase = smb + SO_AHI + a_off;
        const uint32_t alobase = smb + SO_ALO + a_off;
        float acc[2][4][4];
        #pragma unroll
        for (int mb = 0; mb < 2; mb++)
            #pragma unroll
            for (int nb = 0; nb < 4; nb++)
                #pragma unroll
                for (int e = 0; e < 4; e++) acc[mb][nb][e] = 0.0f;

        #pragma unroll
        for (int k = 0; k < 8; k++) {
            uint32_t bfr[2][4];
            #pragma unroll
            for (int nh = 0; nh < 2; nh++)
                ldsm4(bfr[nh], bbase + nh * 16 * ROWB + k * 32);
            uint32_t ahi[2][4], alo[2][4];
            #pragma unroll
            for (int mb = 0; mb < 2; mb++) {
                ldsm4(ahi[mb], ahibase + mb * 16 * ROWB + k * 32);
                ldsm4(alo[mb], alobase + mb * 16 * ROWB + k * 32);
            }
            #pragma unroll
            for (int nb = 0; nb < 4; nb++) {
                uint32_t b0 = bfr[nb >> 1][(nb & 1) * 2];
                uint32_t b1 = bfr[nb >> 1][(nb & 1) * 2 + 1];
                mma16816(acc[0][nb], ahi[0], b0, b1);
                mma16816(acc[1][nb], ahi[1], b0, b1);
            }
            #pragma unroll
            for (int nb = 0; nb < 4; nb++) {
                uint32_t b0 = bfr[nb >> 1][(nb & 1) * 2];
                uint32_t b1 = bfr[nb >> 1][(nb & 1) * 2 + 1];
                mma16816(acc[0][nb], alo[0], b0, b1);
                mma16816(acc[1][nb], alo[1], b0, b1);
            }
        }

        // ---- epilogue: squared distance + masked running max/min ----
        const float* sjp = s_j + p * 128;
        const unsigned char* smp = s_mask + p * 128;
        #pragma unroll
        for (int nb = 0; nb < 4; nb++) {
            int col0 = warp_n + nb * 8 + 2 * tr;
            float c2a = sjp[col0];
            float c2b = sjp[col0 + 1];
            bool pa = (smp[col0] != 0);
            bool pb = (smp[col0 + 1] != 0);
            #pragma unroll
            for (int mb = 0; mb < 2; mb++) {
                float b0 = r1v[mb * 2 + 0];
                float b1 = r1v[mb * 2 + 1];
                float s00 = fmaf(acc[mb][nb][0], -2.0f, b0 + c2a);
                float s01 = fmaf(acc[mb][nb][1], -2.0f, b0 + c2b);
                float s10 = fmaf(acc[mb][nb][2], -2.0f, b1 + c2a);
                float s11 = fmaf(acc[mb][nb][3], -2.0f, b1 + c2b);
                if (pa) { pmax[mb*2]   = fmaxf(pmax[mb*2],   s00);
                          pmax[mb*2+1] = fmaxf(pmax[mb*2+1], s10); }
                else    { nmin[mb*2]   = fminf(nmin[mb*2],   s00);
                          nmin[mb*2+1] = fminf(nmin[mb*2+1], s10); }
                if (pb) { pmax[mb*2]   = fmaxf(pmax[mb*2],   s01);
                          pmax[mb*2+1] = fmaxf(pmax[mb*2+1], s11); }
                else    { nmin[mb*2]   = fminf(nmin[mb*2],   s01);
                          nmin[mb*2+1] = fminf(nmin[mb*2+1], s11); }
            }
        }
        p ^= 1;
    }

    // final flush
    if (cur_i >= 0) {
        #pragma unroll
        for (int idx = 0; idx < 4; idx++) {
            float pv = pmax[idx], nv = nmin[idx];
            pv = fmaxf(pv, __shfl_xor_sync(0xffffffffu, pv, 1));
            pv = fmaxf(pv, __shfl_xor_sync(0xffffffffu, pv, 2));
            nv = fminf(nv, __shfl_xor_sync(0xffffffffu, nv, 1));
            nv = fminf(nv, __shfl_xor_sync(0xffffffffu, nv, 2));
            if (tr == 0) {
                int row = i0 + warp_m + (idx >> 1) * 16 + (idx & 1) * 8 + tq;
                atomicMax(reinterpret_cast<int*>(&g_posmax[row]), __float_as_int(pv));
                atomicMin(reinterpret_cast<int*>(&g_negmin[row]), __float_as_int(nv));
            }
        }
    }

    // ---- last-CTA finalization ----
    __threadfence();
    __syncthreads();
    __shared__ unsigned int s_ticket;
    if (tid == 0) s_ticket = atomicAdd(&g_done, 1u);
    __syncthreads();
    if (s_ticket == GRID_MAIN - 1) {
        __threadfence();
        __shared__ float ssum[NTHREADS];
        __shared__ float scnt[NTHREADS];
        float s = 0.0f, c = 0.0f;
        for (int i = tid; i < BATCH; i += NTHREADS) {
            if (g_tmask[i]) {
                float pm = sqrtf(fmaxf(__int_as_float((int)g_posmax[i]), 0.0f));
                float nm = sqrtf(fmaxf(__int_as_float((int)g_negmin[i]), 0.0f));
                s += fmaxf(pm - nm + MARGIN, 0.0f);
                c += 1.0f;
            }
        }
        ssum[tid] = s;
        scnt[tid] = c;
        __syncthreads();
        for (int st = NTHREADS / 2; st > 0; st >>= 1) {
            if (tid < st) { ssum[tid] += ssum[tid + st]; scnt[tid] += scnt[tid + st]; }
            __syncthreads();
        }
        if (tid == 0) out[0] = ssum[0] / scnt[0];
    }
}

extern "C" void kernel_launch(void* const* d_in, const int* in_sizes, int n_in,
                              void* d_out, int out_size) {
    const float* e1 = (const float*)d_in[0];
    const float* e2 = (const float*)d_in[1];
    const int* tgt = (const int*)d_in[2];
    float* out = (float*)d_out;

    cudaFuncSetAttribute(bht_mma_kernel,
                         cudaFuncAttributeMaxDynamicSharedMemorySize, SMEM_TOTAL);

    prep_kernel<<<(2 * BATCH) / 8, 256>>>(e1, e2, tgt);
    bht_mma_kernel<<<GRID_MAIN, NTHREADS, SMEM_TOTAL>>>(out);
}

// round 12
// speedup vs baseline: 1.7782x; 1.7782x over previous
#include <cuda_runtime.h>
#include <cuda_fp16.h>
#include <math_constants.h>
#include <cstdint>

#define BATCH 8192
#define DIM 128
#define MARGIN 0.2f
#define EPSV 1e-6f

#define NJT 64
#define NIT 64
#define NJOBS (NIT * NJT)
#define GRID_MAIN 152
#define NTHREADS 256

// SMEM: fp16 tiles, row stride 272 B (conflict-free LDSM), double-buffered B
#define ROWB 272
#define TILE_BYTES (128 * ROWB)          // 34816
#define SO_SJ   0                        // 2 x 512 B (j row-constants)
#define SO_MASK 1024                     // 2 x 128 B
#define SO_A    2048
#define SO_B0   (SO_A + TILE_BYTES)      // 36864
#define SO_B1   (SO_B0 + TILE_BYTES)     // 71680
#define SMEM_TOTAL (SO_B1 + TILE_BYTES)  // 106496

// ---------------------------------------------------------------------------
// Scratch (device allocation forbidden)
// ---------------------------------------------------------------------------
__device__ float g_r1[BATCH];
__device__ float g_r2[BATCH];
__device__ unsigned int g_posmax[BATCH];   // float bits of max sq-dist (positives)
__device__ unsigned int g_negmin[BATCH];   // float bits of min sq-dist (negatives)
__device__ __align__(16) unsigned char g_tmask[BATCH];
__device__ unsigned int g_done;
__device__ __align__(16) __half g_e1h[BATCH * DIM];
__device__ __align__(16) __half g_e2h[BATCH * DIM];

// ---------------------------------------------------------------------------
// PTX helpers (base ISA: ldmatrix, mma.sync, cp.async)
// ---------------------------------------------------------------------------
__device__ __forceinline__ uint32_t smem_to_u32(const void* p) {
    uint32_t a;
    asm("{ .reg .u64 t; cvta.to.shared.u64 t, %1; cvt.u32.u64 %0, t; }" : "=r"(a) : "l"(p));
    return a;
}
__device__ __forceinline__ void ldsm4(uint32_t* r, uint32_t addr) {
    asm volatile("ldmatrix.sync.aligned.m8n8.x4.shared.b16 {%0,%1,%2,%3}, [%4];"
                 : "=r"(r[0]), "=r"(r[1]), "=r"(r[2]), "=r"(r[3]) : "r"(addr));
}
__device__ __forceinline__ void mma16816(float* c, const uint32_t* a,
                                         uint32_t b0, uint32_t b1) {
    asm volatile(
        "mma.sync.aligned.m16n8k16.row.col.f32.f16.f16.f32 "
        "{%0,%1,%2,%3}, {%4,%5,%6,%7}, {%8,%9}, {%0,%1,%2,%3};"
        : "+f"(c[0]), "+f"(c[1]), "+f"(c[2]), "+f"(c[3])
        : "r"(a[0]), "r"(a[1]), "r"(a[2]), "r"(a[3]), "r"(b0), "r"(b1));
}
__device__ __forceinline__ void cp16(uint32_t dst, const void* src) {
    asm volatile("cp.async.cg.shared.global [%0], [%1], 16;" :: "r"(dst), "l"(src));
}
#define CP_COMMIT() asm volatile("cp.async.commit_group;" ::: "memory")
#define CP_WAIT_ALL() asm volatile("cp.async.wait_group 0;" ::: "memory")

// ---------------------------------------------------------------------------
// prep: row constants, reduction init, mask (int32 target), fp16 round.
// One warp per row, 2*BATCH rows. Also resets the completion ticket.
// ---------------------------------------------------------------------------
__global__ void prep_kernel(const float* __restrict__ e1,
                            const float* __restrict__ e2,
                            const int* __restrict__ t32) {
    if (blockIdx.x == 0 && threadIdx.x == 0) g_done = 0u;
    int warp = (blockIdx.x * blockDim.x + threadIdx.x) >> 5;
    int lane = threadIdx.x & 31;
    if (warp >= 2 * BATCH) return;
    bool is1 = (warp < BATCH);
    int row = is1 ? warp : warp - BATCH;
    const float* base = is1 ? e1 : e2;
    float4 v = reinterpret_cast<const float4*>(base + (size_t)row * DIM)[lane];

    __half2 hp0 = __floats2half2_rn(v.x, v.y);
    __half2 hp1 = __floats2half2_rn(v.z, v.w);
    __half* dh = is1 ? g_e1h : g_e2h;
    int idx = row * DIM + lane * 4;
    *reinterpret_cast<__half2*>(&dh[idx])     = hp0;
    *reinterpret_cast<__half2*>(&dh[idx + 2]) = hp1;

    float s = v.x + v.y + v.z + v.w;
    float q = v.x * v.x + v.y * v.y + v.z * v.z + v.w * v.w;
    #pragma unroll
    for (int o = 16; o > 0; o >>= 1) {
        s += __shfl_xor_sync(0xffffffffu, s, o);
        q += __shfl_xor_sync(0xffffffffu, q, o);
    }
    if (lane == 0) {
        if (is1) {
            g_r1[row] = q + 2.0f * EPSV * s + (float)DIM * EPSV * EPSV;
            g_posmax[row] = 0xFF800000u;
            g_negmin[row] = 0x7F800000u;
            g_tmask[row] = (t32[row] == 1) ? 1 : 0;
        } else {
            g_r2[row] = q - 2.0f * EPSV * s;
        }
    }
}

// ---------------------------------------------------------------------------
// Main: persistent CTAs, single-pass fp16 mma.sync GEMM + sq-dist max/min.
// 8 warps as 4(m) x 2(n); warp tile 32x64. A fragments cached in registers
// per i-strip; B double-buffered via cp.async. Last CTA folds in finalize.
// ---------------------------------------------------------------------------
extern __shared__ char sm_dyn[];

__device__ __forceinline__ void issue_tile(uint32_t smb, int off, const __half* g,
                                           int row0, int tid) {
    #pragma unroll
    for (int t = 0; t < 8; t++) {
        int i = tid + t * NTHREADS;
        int row = i >> 4;
        int c = i & 15;
        cp16(smb + off + row * ROWB + c * 16, g + (size_t)(row0 + row) * DIM + c * 8);
    }
}

__global__ __launch_bounds__(NTHREADS, 1) void bht_mma_kernel(float* __restrict__ out) {
    char* sm = sm_dyn;
    const uint32_t smb = smem_to_u32(sm);
    float* s_j = reinterpret_cast<float*>(sm + SO_SJ);
    unsigned char* s_mask = reinterpret_cast<unsigned char*>(sm + SO_MASK);

    const int tid = threadIdx.x;
    const int wid = tid >> 5;
    const int lane = tid & 31;
    const int tq = lane >> 2;
    const int tr = lane & 3;
    const int warp_m = (wid >> 1) * 32;
    const int warp_n = (wid & 1) * 64;

    const int a_off = (warp_m + (lane & 15)) * ROWB + (lane >> 4) * 16;
    const int b_off = (warp_n + (lane & 7) + ((lane >> 4) << 3)) * ROWB
                    + ((lane >> 3) & 1) * 16;

    const int job0 = (NJOBS * blockIdx.x) / GRID_MAIN;
    const int jend = (NJOBS * (blockIdx.x + 1)) / GRID_MAIN;

    int cur_i = -1, i0 = 0, p = 0;
    uint32_t af[8][2][4];                 // A fragments cached across the i-strip
    float r1v[4], pmax[4], nmin[4];

    // prologue: first job's B tile + row constants into slot 0
    {
        const int j0 = (job0 & (NJT - 1)) * 128;
        issue_tile(smb, SO_B0, g_e2h, j0, tid);
        if (tid < 32) cp16(smb + SO_SJ + tid * 16, g_r2 + j0 + tid * 4);
        else if (tid < 40) cp16(smb + SO_MASK + (tid - 32) * 16, g_tmask + j0 + (tid - 32) * 16);
        CP_COMMIT();
    }

    for (int job = job0; job < jend; ++job) {
        const int it = job >> 6;
        bool ichg = (it != cur_i);

        if (ichg) {
            // flush previous strip
            if (cur_i >= 0) {
                #pragma unroll
                for (int idx = 0; idx < 4; idx++) {
                    float pv = pmax[idx], nv = nmin[idx];
                    pv = fmaxf(pv, __shfl_xor_sync(0xffffffffu, pv, 1));
                    pv = fmaxf(pv, __shfl_xor_sync(0xffffffffu, pv, 2));
                    nv = fminf(nv, __shfl_xor_sync(0xffffffffu, nv, 1));
                    nv = fminf(nv, __shfl_xor_sync(0xffffffffu, nv, 2));
                    if (tr == 0) {
                        int row = i0 + warp_m + (idx >> 1) * 16 + (idx & 1) * 8 + tq;
                        atomicMax(reinterpret_cast<int*>(&g_posmax[row]), __float_as_int(pv));
                        atomicMin(reinterpret_cast<int*>(&g_negmin[row]), __float_as_int(nv));
                    }
                }
            }
            i0 = it * 128;
            __syncthreads();   // all readers done with old A before overwrite
            issue_tile(smb, SO_A, g_e1h, i0, tid);
            CP_COMMIT();
        }

        CP_WAIT_ALL();
        __syncthreads();       // slot p (and A, if reloaded) visible to all

        if (ichg) {
            #pragma unroll
            for (int k = 0; k < 8; k++)
                #pragma unroll
                for (int mb = 0; mb < 2; mb++)
                    ldsm4(af[k][mb], smb + SO_A + a_off + mb * 16 * ROWB + k * 32);
            #pragma unroll
            for (int idx = 0; idx < 4; idx++) {
                int row = i0 + warp_m + (idx >> 1) * 16 + (idx & 1) * 8 + tq;
                r1v[idx] = g_r1[row];
                pmax[idx] = -CUDART_INF_F;
                nmin[idx] = CUDART_INF_F;
            }
            cur_i = it;
        }

        // issue next job's B into the other slot (overlaps with compute below)
        if (job + 1 < jend) {
            const int nj0 = ((job + 1) & (NJT - 1)) * 128;
            const int so_b = p ? SO_B0 : SO_B1;
            const int so_j = SO_SJ + (p ^ 1) * 512;
            const int so_m = SO_MASK + (p ^ 1) * 128;
            issue_tile(smb, so_b, g_e2h, nj0, tid);
            if (tid < 32) cp16(smb + so_j + tid * 16, g_r2 + nj0 + tid * 4);
            else if (tid < 40) cp16(smb + so_m + (tid - 32) * 16, g_tmask + nj0 + (tid - 32) * 16);
            CP_COMMIT();
        }

        // ---- compute on slot p (single fp16 pass) ----
        const uint32_t bbase = smb + (p ? SO_B1 : SO_B0) + b_off;
        float acc[2][8][4];
        #pragma unroll
        for (int mb = 0; mb < 2; mb++)
            #pragma unroll
            for (int nb = 0; nb < 8; nb++)
                #pragma unroll
                for (int e = 0; e < 4; e++) acc[mb][nb][e] = 0.0f;

        #pragma unroll
        for (int k = 0; k < 8; k++) {
            uint32_t bfr[4][4];
            #pragma unroll
            for (int nh = 0; nh < 4; nh++)
                ldsm4(bfr[nh], bbase + nh * 16 * ROWB + k * 32);
            #pragma unroll
            for (int nb = 0; nb < 8; nb++) {
                uint32_t b0 = bfr[nb >> 1][(nb & 1) * 2];
                uint32_t b1 = bfr[nb >> 1][(nb & 1) * 2 + 1];
                mma16816(acc[0][nb], af[k][0], b0, b1);
                mma16816(acc[1][nb], af[k][1], b0, b1);
            }
        }

        // ---- epilogue: squared distance + masked running max/min ----
        const float* sjp = s_j + p * 128;
        const unsigned char* smp = s_mask + p * 128;
        #pragma unroll
        for (int nb = 0; nb < 8; nb++) {
            int col0 = warp_n + nb * 8 + 2 * tr;
            float c2a = sjp[col0];
            float c2b = sjp[col0 + 1];
            bool pa = (smp[col0] != 0);
            bool pb = (smp[col0 + 1] != 0);
            #pragma unroll
            for (int mb = 0; mb < 2; mb++) {
                float b0 = r1v[mb * 2 + 0];
                float b1 = r1v[mb * 2 + 1];
                float s00 = fmaf(acc[mb][nb][0], -2.0f, b0 + c2a);
                float s01 = fmaf(acc[mb][nb][1], -2.0f, b0 + c2b);
                float s10 = fmaf(acc[mb][nb][2], -2.0f, b1 + c2a);
                float s11 = fmaf(acc[mb][nb][3], -2.0f, b1 + c2b);
                if (pa) { pmax[mb*2]   = fmaxf(pmax[mb*2],   s00);
                          pmax[mb*2+1] = fmaxf(pmax[mb*2+1], s10); }
                else    { nmin[mb*2]   = fminf(nmin[mb*2],   s00);
                          nmin[mb*2+1] = fminf(nmin[mb*2+1], s10); }
                if (pb) { pmax[mb*2]   = fmaxf(pmax[mb*2],   s01);
                          pmax[mb*2+1] = fmaxf(pmax[mb*2+1], s11); }
                else    { nmin[mb*2]   = fminf(nmin[mb*2],   s01);
                          nmin[mb*2+1] = fminf(nmin[mb*2+1], s11); }
            }
        }
        p ^= 1;
    }

    // final flush
    if (cur_i >= 0) {
        #pragma unroll
        for (int idx = 0; idx < 4; idx++) {
            float pv = pmax[idx], nv = nmin[idx];
            pv = fmaxf(pv, __shfl_xor_sync(0xffffffffu, pv, 1));
            pv = fmaxf(pv, __shfl_xor_sync(0xffffffffu, pv, 2));
            nv = fminf(nv, __shfl_xor_sync(0xffffffffu, nv, 1));
            nv = fminf(nv, __shfl_xor_sync(0xffffffffu, nv, 2));
            if (tr == 0) {
                int row = i0 + warp_m + (idx >> 1) * 16 + (idx & 1) * 8 + tq;
                atomicMax(reinterpret_cast<int*>(&g_posmax[row]), __float_as_int(pv));
                atomicMin(reinterpret_cast<int*>(&g_negmin[row]), __float_as_int(nv));
            }
        }
    }

    // ---- last-CTA finalization ----
    __threadfence();
    __syncthreads();
    __shared__ unsigned int s_ticket;
    if (tid == 0) s_ticket = atomicAdd(&g_done, 1u);
    __syncthreads();
    if (s_ticket == GRID_MAIN - 1) {
        __threadfence();
        __shared__ float ssum[NTHREADS];
        __shared__ float scnt[NTHREADS];
        float s = 0.0f, c = 0.0f;
        for (int i = tid; i < BATCH; i += NTHREADS) {
            if (g_tmask[i]) {
                float pm = sqrtf(fmaxf(__int_as_float((int)g_posmax[i]), 0.0f));
                float nm = sqrtf(fmaxf(__int_as_float((int)g_negmin[i]), 0.0f));
                s += fmaxf(pm - nm + MARGIN, 0.0f);
                c += 1.0f;
            }
        }
        ssum[tid] = s;
        scnt[tid] = c;
        __syncthreads();
        for (int st = NTHREADS / 2; st > 0; st >>= 1) {
            if (tid < st) { ssum[tid] += ssum[tid + st]; scnt[tid] += scnt[tid + st]; }
            __syncthreads();
        }
        if (tid == 0) out[0] = ssum[0] / scnt[0];
    }
}

extern "C" void kernel_launch(void* const* d_in, const int* in_sizes, int n_in,
                              void* d_out, int out_size) {
    const float* e1 = (const float*)d_in[0];
    const float* e2 = (const float*)d_in[1];
    const int* tgt = (const int*)d_in[2];
    float* out = (float*)d_out;

    cudaFuncSetAttribute(bht_mma_kernel,
                         cudaFuncAttributeMaxDynamicSharedMemorySize, SMEM_TOTAL);

    prep_kernel<<<(2 * BATCH) / 8, 256>>>(e1, e2, tgt);
    bht_mma_kernel<<<GRID_MAIN, NTHREADS, SMEM_TOTAL>>>(out);
}